// round 5
// baseline (speedup 1.0000x reference)
#include <cuda_runtime.h>

// RWKV WKV single-pass decoupled-lookback scan (ticket-ordered, deadlock-free).
//   a_t = d_t * a_{t-1} + ek_t * v_t ;  b_t = d_t * b_{t-1} + ek_t
//   out = sigmoid(r) * a / (b + eps),  d = exp(-exp(w)), ek = exp(k)
//
// One CTA = one (b, chunk of CLEN timesteps) tile over all C channels, claimed
// via a global ticket so tiles are processed in order by resident CTAs.
// Phase 1: read w,k,v once, stash (d, ek*v, ek) in smem, compose local (D,A,B).
// Publish aggregate -> per-thread lookback for incoming prefix -> publish prefix.
// Phase 2: stream r, replay from smem with carry-in, write out.

#define NB 8
#define NT 4096
#define NC 1024
#define NC4 (NC / 4)            // 256 float4 lanes per row = blockDim
#define CLEN 8                  // timesteps per tile
#define NCHUNK (NT / CLEN)      // 512
#define NTILE (NCHUNK * NB)     // 4096 tiles = grid size
#define WKV_EPS 1e-6f
#define SMEM_BYTES (3 * CLEN * NC4 * 16)   // 96 KB: d, ekv, ek

// Lookback scratch. gFlag[NTILE] doubles as the ticket counter (last slot).
__device__ float4   gAggD[NTILE * NC4];
__device__ float4   gAggA[NTILE * NC4];
__device__ float4   gAggB[NTILE * NC4];
__device__ float4   gPreA[NTILE * NC4];
__device__ float4   gPreB[NTILE * NC4];
__device__ unsigned gFlag[NTILE + 1];      // 0=none, 1=aggregate, 2=prefix

__device__ __forceinline__ unsigned ld_acquire(const unsigned* p) {
    unsigned v;
    asm volatile("ld.global.acquire.gpu.u32 %0, [%1];" : "=r"(v) : "l"(p) : "memory");
    return v;
}
__device__ __forceinline__ void st_release(unsigned* p, unsigned v) {
    asm volatile("st.global.release.gpu.u32 [%0], %1;" :: "l"(p), "r"(v) : "memory");
}

__device__ __forceinline__ float4 f4fma(float4 a, float4 b, float4 c) {
    return make_float4(fmaf(a.x, b.x, c.x), fmaf(a.y, b.y, c.y),
                       fmaf(a.z, b.z, c.z), fmaf(a.w, b.w, c.w));
}
__device__ __forceinline__ float4 f4mul(float4 a, float4 b) {
    return make_float4(a.x * b.x, a.y * b.y, a.z * b.z, a.w * b.w);
}

__global__ void __launch_bounds__(256, 2)
wkv_single(const float4* __restrict__ r, const float4* __restrict__ w,
           const float4* __restrict__ k, const float4* __restrict__ v,
           float4* __restrict__ out) {
    extern __shared__ float4 smem[];
    float4* s_d   = smem;                   // [CLEN][NC4]
    float4* s_ekv = smem + CLEN * NC4;
    float4* s_ek  = smem + 2 * CLEN * NC4;

    // Claim tile in dispatch order: guarantees every predecessor tile is owned
    // by a CTA that is resident (or retired), so lookback cannot deadlock.
    __shared__ unsigned s_tile;
    if (threadIdx.x == 0) s_tile = atomicAdd(&gFlag[NTILE], 1u);
    __syncthreads();
    const int tile  = (int)s_tile;
    const int b     = tile & (NB - 1);
    const int chunk = tile >> 3;            // tile = chunk*NB + b, low chunks first
    const int c4    = threadIdx.x;
    const int base  = (b * NT + chunk * CLEN) * NC4 + c4;

    // ---------------- Phase 1: load once, stash, local aggregate ----------------
    float4 D  = make_float4(1.f, 1.f, 1.f, 1.f);
    float4 A  = make_float4(0.f, 0.f, 0.f, 0.f);
    float4 Bb = make_float4(0.f, 0.f, 0.f, 0.f);

#pragma unroll
    for (int t = 0; t < CLEN; t++) {
        float4 wv = __ldcs(&w[base + t * NC4]);
        float4 kv = __ldcs(&k[base + t * NC4]);
        float4 vv = __ldcs(&v[base + t * NC4]);
        float4 dd, ek, ekv;
        dd.x = __expf(-__expf(wv.x));  ek.x = __expf(kv.x);
        dd.y = __expf(-__expf(wv.y));  ek.y = __expf(kv.y);
        dd.z = __expf(-__expf(wv.z));  ek.z = __expf(kv.z);
        dd.w = __expf(-__expf(wv.w));  ek.w = __expf(kv.w);
        ekv = f4mul(ek, vv);
        A  = f4fma(A, dd, ekv);
        Bb = f4fma(Bb, dd, ek);
        D  = f4mul(D, dd);
        s_d[t * NC4 + c4]   = dd;      // thread-private stash: no sync needed
        s_ekv[t * NC4 + c4] = ekv;
        s_ek[t * NC4 + c4]  = ek;
    }

    const int ps = tile * NC4 + c4;
    float4 Ain = make_float4(0.f, 0.f, 0.f, 0.f);
    float4 Bin = make_float4(0.f, 0.f, 0.f, 0.f);

    if (chunk == 0) {
        // inclusive prefix == local aggregate
        __stcg(&gPreA[ps], A);
        __stcg(&gPreB[ps], Bb);
        __syncthreads();
        if (threadIdx.x == 0) { __threadfence(); st_release(&gFlag[tile], 2u); }
    } else {
        // publish aggregate
        __stcg(&gAggD[ps], D);
        __stcg(&gAggA[ps], A);
        __stcg(&gAggB[ps], Bb);
        __syncthreads();
        if (threadIdx.x == 0) { __threadfence(); st_release(&gFlag[tile], 1u); }

        // ---------------- per-thread decoupled lookback ----------------
        float4 Ds = make_float4(1.f, 1.f, 1.f, 1.f);
        float4 As = make_float4(0.f, 0.f, 0.f, 0.f);
        float4 Bs = make_float4(0.f, 0.f, 0.f, 0.f);
        int j = chunk - 1;
        while (true) {
            const int fj = j * NB + b;
            unsigned st;
            while ((st = ld_acquire(&gFlag[fj])) == 0u) { __nanosleep(64); }
            const int pj = fj * NC4 + c4;
            if (st == 2u) {                       // predecessor inclusive prefix
                float4 Aj = __ldcg(&gPreA[pj]);
                float4 Bj = __ldcg(&gPreB[pj]);
                Ain = f4fma(Aj, Ds, As);
                Bin = f4fma(Bj, Ds, Bs);
                break;
            } else {                              // aggregate only: keep walking
                float4 Dj = __ldcg(&gAggD[pj]);
                float4 Aj = __ldcg(&gAggA[pj]);
                float4 Bj = __ldcg(&gAggB[pj]);
                As = f4fma(Aj, Ds, As);
                Bs = f4fma(Bj, Ds, Bs);
                Ds = f4mul(Ds, Dj);
                if (--j < 0) { Ain = As; Bin = Bs; break; }
            }
        }

        // publish our inclusive prefix
        float4 Ainc = f4fma(Ain, D, A);
        float4 Binc = f4fma(Bin, D, Bb);
        __stcg(&gPreA[ps], Ainc);
        __stcg(&gPreB[ps], Binc);
        __syncthreads();
        if (threadIdx.x == 0) { __threadfence(); st_release(&gFlag[tile], 2u); }
    }

    // ---------------- Phase 2: replay from smem with carry-in ----------------
    float4 a  = Ain;
    float4 bb = Bin;
#pragma unroll
    for (int t = 0; t < CLEN; t++) {
        float4 rv  = __ldcs(&r[base + t * NC4]);
        float4 dd  = s_d[t * NC4 + c4];
        float4 ekv = s_ekv[t * NC4 + c4];
        float4 ek  = s_ek[t * NC4 + c4];
        a  = f4fma(a, dd, ekv);
        bb = f4fma(bb, dd, ek);
        float4 o;
        o.x = __fdividef(a.x, (1.f + __expf(-rv.x)) * (bb.x + WKV_EPS));
        o.y = __fdividef(a.y, (1.f + __expf(-rv.y)) * (bb.y + WKV_EPS));
        o.z = __fdividef(a.z, (1.f + __expf(-rv.z)) * (bb.z + WKV_EPS));
        o.w = __fdividef(a.w, (1.f + __expf(-rv.w)) * (bb.w + WKV_EPS));
        __stcs(&out[base + t * NC4], o);
    }
}

extern "C" void kernel_launch(void* const* d_in, const int* in_sizes, int n_in,
                              void* d_out, int out_size) {
    const float4* r = (const float4*)d_in[0];
    const float4* w = (const float4*)d_in[1];
    const float4* k = (const float4*)d_in[2];
    const float4* v = (const float4*)d_in[3];
    float4* o = (float4*)d_out;

    // Flags + ticket must be re-zeroed on every graph replay.
    void* flagAddr = nullptr;
    cudaGetSymbolAddress(&flagAddr, gFlag);
    cudaMemsetAsync(flagAddr, 0, (NTILE + 1) * sizeof(unsigned));

    cudaFuncSetAttribute(wkv_single,
                         cudaFuncAttributeMaxDynamicSharedMemorySize, SMEM_BYTES);
    wkv_single<<<NTILE, NC4, SMEM_BYTES>>>(r, w, k, v, o);
}

// round 6
// speedup vs baseline: 1.3057x; 1.3057x over previous
#include <cuda_runtime.h>

// RWKV WKV: per-channel affine linear recurrence along T.
//   a_t = d_t * a_{t-1} + ek_t * v_t ;  b_t = d_t * b_{t-1} + ek_t
//   out = sigmoid(r) * a / (b + eps),  d = exp(-exp(w)), ek = exp(k)
//
// 3-pass chunked scan, CLEN=16:
//   (1) per-chunk affine composition  (reads w,k,v = 384 MiB)  [float4/thread]
//   (2) per-channel exclusive scan over 256 chunk summaries (L2-resident)
//   (3) re-stream with carry-in + output (reads r,w,k,v, writes out) [float2/thread]

#define NB 8
#define NT 4096
#define NC 1024
#define NC4 (NC / 4)          // 256 float4 lanes per row
#define NC2 (NC / 2)          // 512 float2 lanes per row
#define NCHUNK 256            // chunks along T
#define CLEN (NT / NCHUNK)    // 16 timesteps per chunk
#define WKV_EPS 1e-6f

// Scratch: chunk summaries, layout [chunk][b][c] (coalesced for all passes).
__device__ float g_D[NCHUNK * NB * NC];   // decay product per chunk
__device__ float g_A[NCHUNK * NB * NC];   // numerator aggregate / excl. prefix
__device__ float g_B[NCHUNK * NB * NC];   // denominator aggregate / excl. prefix

__device__ __forceinline__ void wkv_acc(float wv, float kv, float vv,
                                        float& a, float& b, float& D) {
    float d  = __expf(-__expf(wv));
    float ek = __expf(kv);
    a = fmaf(a, d, ek * vv);
    b = fmaf(b, d, ek);
    D *= d;
}

// One divide total: out = a / ((1 + e^-r) * (b + eps))
__device__ __forceinline__ float wkv_emit(float rv, float wv, float kv, float vv,
                                          float& a, float& b) {
    float d  = __expf(-__expf(wv));
    float ek = __expf(kv);
    a = fmaf(a, d, ek * vv);
    b = fmaf(b, d, ek);
    float denom = (1.0f + __expf(-rv)) * (b + WKV_EPS);
    return __fdividef(a, denom);
}

// ---------------- Pass 1: per-chunk affine composition ----------------
// One thread = 4 channels (float4) x 1 chunk. 524288 threads.
__global__ void __launch_bounds__(256) wkv_pass1(const float4* __restrict__ w,
                                                 const float4* __restrict__ k,
                                                 const float4* __restrict__ v) {
    int tid   = blockIdx.x * 256 + threadIdx.x;
    int c4    = tid & (NC4 - 1);             // bits 0..7  (coalesced)
    int chunk = (tid >> 8) & (NCHUNK - 1);   // bits 8..15
    int b     = tid >> 16;
    int base  = (b * NT + chunk * CLEN) * NC4 + c4;

    float4 D  = make_float4(1.f, 1.f, 1.f, 1.f);
    float4 A  = make_float4(0.f, 0.f, 0.f, 0.f);
    float4 Bb = make_float4(0.f, 0.f, 0.f, 0.f);

#pragma unroll 4
    for (int t = 0; t < CLEN; t++) {
        float4 wv = __ldcs(&w[base + t * NC4]);
        float4 kv = __ldcs(&k[base + t * NC4]);
        float4 vv = __ldcs(&v[base + t * NC4]);
        wkv_acc(wv.x, kv.x, vv.x, A.x, Bb.x, D.x);
        wkv_acc(wv.y, kv.y, vv.y, A.y, Bb.y, D.y);
        wkv_acc(wv.z, kv.z, vv.z, A.z, Bb.z, D.z);
        wkv_acc(wv.w, kv.w, vv.w, A.w, Bb.w, D.w);
    }

    int s = (chunk * NB + b) * NC4 + c4;
    reinterpret_cast<float4*>(g_D)[s] = D;
    reinterpret_cast<float4*>(g_A)[s] = A;
    reinterpret_cast<float4*>(g_B)[s] = Bb;
}

// ---------------- Pass 2: exclusive scan over chunk summaries ----------------
// One thread per channel (NB*NC = 8192). Scratch is L2-resident (24 MiB).
__global__ void __launch_bounds__(256) wkv_pass2() {
    int tid = blockIdx.x * 256 + threadIdx.x;
    int c   = tid & (NC - 1);
    int b   = tid >> 10;

    float Ap = 0.f, Bp = 0.f;
#pragma unroll 4
    for (int ch = 0; ch < NCHUNK; ch++) {
        int idx = (ch * NB + b) * NC + c;
        float d  = g_D[idx];
        float a  = g_A[idx];
        float bb = g_B[idx];
        g_A[idx] = Ap;                 // exclusive prefix (state entering chunk)
        g_B[idx] = Bp;
        Ap = fmaf(Ap, d, a);
        Bp = fmaf(Bp, d, bb);
    }
}

// ---------------- Pass 3: re-stream with carry-in, emit output ----------------
// One thread = 2 channels (float2) x 1 chunk. 1,048,576 threads, unroll 4:
// 16 LDG.64 in flight per thread at modest register cost.
__global__ void __launch_bounds__(256) wkv_pass3(const float2* __restrict__ r,
                                                 const float2* __restrict__ w,
                                                 const float2* __restrict__ k,
                                                 const float2* __restrict__ v,
                                                 float2* __restrict__ out) {
    int tid   = blockIdx.x * 256 + threadIdx.x;
    int c2    = tid & (NC2 - 1);             // bits 0..8 (coalesced)
    int chunk = (tid >> 9) & (NCHUNK - 1);   // bits 9..16
    int b     = tid >> 17;

    int s = (chunk * NB + b) * NC2 + c2;
    float2 A  = reinterpret_cast<const float2*>(g_A)[s];
    float2 Bb = reinterpret_cast<const float2*>(g_B)[s];

    int base = (b * NT + chunk * CLEN) * NC2 + c2;
#pragma unroll 4
    for (int t = 0; t < CLEN; t++) {
        int idx = base + t * NC2;
        float2 rv = __ldcs(&r[idx]);
        float2 wv = __ldcs(&w[idx]);
        float2 kv = __ldcs(&k[idx]);
        float2 vv = __ldcs(&v[idx]);
        float2 o;
        o.x = wkv_emit(rv.x, wv.x, kv.x, vv.x, A.x, Bb.x);
        o.y = wkv_emit(rv.y, wv.y, kv.y, vv.y, A.y, Bb.y);
        __stcs(&out[idx], o);
    }
}

extern "C" void kernel_launch(void* const* d_in, const int* in_sizes, int n_in,
                              void* d_out, int out_size) {
    const float4* w4 = (const float4*)d_in[1];
    const float4* k4 = (const float4*)d_in[2];
    const float4* v4 = (const float4*)d_in[3];
    const float2* r2 = (const float2*)d_in[0];
    const float2* w2 = (const float2*)d_in[1];
    const float2* k2 = (const float2*)d_in[2];
    const float2* v2 = (const float2*)d_in[3];
    float2* o2 = (float2*)d_out;

    const int n1 = NB * NC4 * NCHUNK;    // 524288 threads, 2048 blocks
    const int n3 = NB * NC2 * NCHUNK;    // 1048576 threads, 4096 blocks
    wkv_pass1<<<n1 / 256, 256>>>(w4, k4, v4);
    wkv_pass2<<<(NB * NC) / 256, 256>>>();
    wkv_pass3<<<n3 / 256, 256>>>(r2, w2, k2, v2, o2);
}

// round 7
// speedup vs baseline: 1.6965x; 1.2993x over previous
#include <cuda_runtime.h>

// RWKV WKV single-pass warp-scan.
//   a_t = d_t * a_{t-1} + ek_t * v_t ;  b_t = d_t * b_{t-1} + ek_t
//   out = sigmoid(r) * a / (b + eps),  d = exp(-exp(w)), ek = exp(k)
//
// CTA = (batch, 16-channel block) x full T. Warp w owns channel c0+w.
// Per 64-timestep tile: coalesced float2 loads -> smem transpose (padded,
// conflict-free) -> per-warp Kogge-Stone shuffle scan of affine maps (D,A,B)
// over 32 lanes (x2 blocks) with register carry -> smem transpose -> stores.
// Reads each input exactly once: 640 MiB total traffic (vs 1.07 GiB 3-pass).

#define B_     8
#define T_     4096
#define C_     1024
#define CBLK   16                 // channels per CTA (= warps per CTA)
#define TTILE  64                 // timesteps per iteration
#define NITER  (T_ / TTILE)       // 64
#define THREADS 512
#define SROW   66                 // padded smem row stride -> conflict-free
#define WKV_EPS 1e-6f

__global__ void __launch_bounds__(THREADS, 2)
wkv_warpscan(const float2* __restrict__ r, const float2* __restrict__ w,
             const float2* __restrict__ k, const float2* __restrict__ v,
             float2* __restrict__ out) {
    __shared__ float sw[2][CBLK * SROW];
    __shared__ float sk[2][CBLK * SROW];
    __shared__ float sv[2][CBLK * SROW];
    __shared__ float sr[2][CBLK * SROW];
    __shared__ float so[CBLK * SROW];

    const int tid  = threadIdx.x;
    const int lane = tid & 31;
    const int wid  = tid >> 5;            // 0..15: warp's channel row
    const int tl   = tid >> 3;            // 0..63: t-row for load/store
    const int cl2  = tid & 7;             // float2 channel-pair index

    const int b  = blockIdx.x >> 6;       // 8 batches
    const int c0 = (blockIdx.x & 63) * CBLK;

    const int rowF2 = C_ / 2;             // float2 per time row
    const int gco   = (b * T_) * rowF2 + (c0 >> 1) + cl2;   // + t*rowF2

    // Transposed STS/LDS addresses: thread covers channels 2*cl2, 2*cl2+1 @ col tl.
    // Bank math (SROW=66): (2*cl2*66 + tl) % 32 = (4*cl2 + tl) % 32 -> all 32
    // lanes distinct (cl2 in 0..7, tl in 0..3 per warp). Conflict-free.
    const int stA = (2 * cl2) * SROW + tl;
    const int stB = stA + SROW;

    // Prefetch tile 0 into registers.
    float2 rw = __ldcs(&w[gco + tl * rowF2]);
    float2 rk = __ldcs(&k[gco + tl * rowF2]);
    float2 rv = __ldcs(&v[gco + tl * rowF2]);
    float2 rr = __ldcs(&r[gco + tl * rowF2]);

    float aC = 0.f, bC = 0.f;             // per-warp scan carry (a, b state)

    for (int it = 0; it < NITER; ++it) {
        const int buf = it & 1;

        // Stage current tile into smem (transposed).
        sw[buf][stA] = rw.x;  sw[buf][stB] = rw.y;
        sk[buf][stA] = rk.x;  sk[buf][stB] = rk.y;
        sv[buf][stA] = rv.x;  sv[buf][stB] = rv.y;
        sr[buf][stA] = rr.x;  sr[buf][stB] = rr.y;

        // Prefetch next tile (overlaps with compute below).
        if (it + 1 < NITER) {
            const int g = gco + ((it + 1) * TTILE + tl) * rowF2;
            rw = __ldcs(&w[g]);  rk = __ldcs(&k[g]);
            rv = __ldcs(&v[g]);  rr = __ldcs(&r[g]);
        }
        __syncthreads();

        // Each warp scans its channel: 2 blocks of 32 timesteps.
#pragma unroll
        for (int blk = 0; blk < 2; ++blk) {
            const int si = wid * SROW + blk * 32 + lane;
            float wv  = sw[buf][si];
            float kv  = sk[buf][si];
            float vv  = sv[buf][si];
            float rv_ = sr[buf][si];

            float dd = __expf(-__expf(wv));
            float ek = __expf(kv);
            float D = dd, A = ek * vv, Bv = ek;

            // Inclusive Kogge-Stone over affine composition (earlier ∘ current):
            //   D = Dp*D ; A = Ap*D + A ; B = Bp*D + B   (use old D in the fmas)
#pragma unroll
            for (int s = 1; s < 32; s <<= 1) {
                float Dp = __shfl_up_sync(0xffffffffu, D, s);
                float Ap = __shfl_up_sync(0xffffffffu, A, s);
                float Bp = __shfl_up_sync(0xffffffffu, Bv, s);
                if (lane >= s) {
                    A  = fmaf(Ap, D, A);
                    Bv = fmaf(Bp, D, Bv);
                    D *= Dp;
                }
            }
            // Apply incoming carry, then extract new carry from lane 31.
            A  = fmaf(aC, D, A);
            Bv = fmaf(bC, D, Bv);
            aC = __shfl_sync(0xffffffffu, A, 31);
            bC = __shfl_sync(0xffffffffu, Bv, 31);

            // out = a / ((1 + e^-r) * (b + eps))  == sigmoid(r)*a/(b+eps)
            so[si] = __fdividef(A, (1.f + __expf(-rv_)) * (Bv + WKV_EPS));
        }
        __syncthreads();

        // Transposed read-back + coalesced store.
        float2 o2 = make_float2(so[stA], so[stB]);
        __stcs(&out[gco + (it * TTILE + tl) * rowF2], o2);
        // so overwrite next iter is guarded by the sync after its STS-in stage.
    }
}

extern "C" void kernel_launch(void* const* d_in, const int* in_sizes, int n_in,
                              void* d_out, int out_size) {
    const float2* r = (const float2*)d_in[0];
    const float2* w = (const float2*)d_in[1];
    const float2* k = (const float2*)d_in[2];
    const float2* v = (const float2*)d_in[3];
    float2* o = (float2*)d_out;

    const int grid = B_ * (C_ / CBLK);    // 512 CTAs
    wkv_warpscan<<<grid, THREADS>>>(r, w, k, v, o);
}

// round 8
// speedup vs baseline: 2.1362x; 1.2592x over previous
#include <cuda_runtime.h>

// RWKV WKV single-pass warp-scan, v2: float4 global access (full 128B lines),
// serial-2 hybrid shuffle scan (21 SHFL / 64 elements), skewed smem layout
// (bank-conflict-free STS/LDS on both transpose directions).
//
//   a_t = d_t * a_{t-1} + ek_t * v_t ;  b_t = d_t * b_{t-1} + ek_t
//   out = sigmoid(r) * a / (b + eps),  d = exp(-exp(w)), ek = exp(k)
//
// CTA = (batch, 32-channel block) x full T, 256 threads (8 warps).
// Warp owns 4 channels; per 64-t tile each lane owns t=2L,2L+1 of one channel.

#define B_      8
#define T_      4096
#define C_      1024
#define CBLK    32
#define TTILE   64
#define NITER   (T_ / TTILE)      // 64
#define THREADS 256
#define SROW    66                // even (8B-aligned pairs), skew fixes banks
#define REGF    (CBLK * SROW)     // 2112 floats per region
#define SMEMB   (9 * REGF * 4)    // 4 streams x 2 bufs + so = 76032 B
#define WKV_EPS 1e-6f

// Skewed transpose address: banks distinct for writer pattern (12*cl4+2j+t)
// and reader pattern (LDS.64 over lanes). Wrap is mod 64 (multiple of 32 banks).
__device__ __forceinline__ int saddr(int ch, int t) {
    return ch * SROW + ((t + 4 * (ch >> 2)) & 63);
}

__global__ void __launch_bounds__(THREADS, 2)
wkv_scan2(const float4* __restrict__ r, const float4* __restrict__ w,
          const float4* __restrict__ k, const float4* __restrict__ v,
          float4* __restrict__ out) {
    extern __shared__ float S[];
    // regions: stream s, buffer b -> S + (s*2+b)*REGF ; so -> S + 8*REGF
    float* so = S + 8 * REGF;

    const int tid  = threadIdx.x;
    const int lane = tid & 31;
    const int wid  = tid >> 5;          // 0..7: warp owns channels 4*wid..+3
    const int cl4  = tid & 7;           // float4 column for loads
    const int tl   = tid >> 3;          // 0..31: t-row for loads (also tl+32)

    const int b  = blockIdx.x >> 5;     // 8 batches
    const int c0 = (blockIdx.x & 31) * CBLK;

    const int rowF4 = C_ / 4;           // 256 float4 per time row
    const int gco   = (b * T_) * rowF4 + (c0 >> 2) + cl4;   // + t*rowF4

    // Prefetch tile 0 (2 rows per thread per stream).
    float4 pw[2], pk[2], pv[2], pr[2];
#pragma unroll
    for (int rr = 0; rr < 2; ++rr) {
        const int g = gco + (tl + rr * 32) * rowF4;
        pw[rr] = __ldcs(&w[g]);  pk[rr] = __ldcs(&k[g]);
        pv[rr] = __ldcs(&v[g]);  pr[rr] = __ldcs(&r[g]);
    }

    float aC[4] = {0.f, 0.f, 0.f, 0.f};   // per-owned-channel scan carries
    float bC[4] = {0.f, 0.f, 0.f, 0.f};

    for (int it = 0; it < NITER; ++it) {
        const int bf = it & 1;
        float* sw = S + (0 * 2 + bf) * REGF;
        float* sk = S + (1 * 2 + bf) * REGF;
        float* sv = S + (2 * 2 + bf) * REGF;
        float* sr = S + (3 * 2 + bf) * REGF;

        // ---- stage current tile (transposed, skewed) ----
#pragma unroll
        for (int rr = 0; rr < 2; ++rr) {
            const int t = tl + rr * 32;
#pragma unroll
            for (int j = 0; j < 4; ++j) {
                const int a = saddr(4 * cl4 + j, t);
                sw[a] = ((const float*)&pw[rr])[j];
                sk[a] = ((const float*)&pk[rr])[j];
                sv[a] = ((const float*)&pv[rr])[j];
                sr[a] = ((const float*)&pr[rr])[j];
            }
        }
        // ---- prefetch next tile ----
        if (it + 1 < NITER) {
#pragma unroll
            for (int rr = 0; rr < 2; ++rr) {
                const int g = gco + ((it + 1) * TTILE + tl + rr * 32) * rowF4;
                pw[rr] = __ldcs(&w[g]);  pk[rr] = __ldcs(&k[g]);
                pv[rr] = __ldcs(&v[g]);  pr[rr] = __ldcs(&r[g]);
            }
        }
        __syncthreads();

        // ---- per-warp serial-2 hybrid scan, 4 channels ----
#pragma unroll
        for (int sub = 0; sub < 4; ++sub) {
            const int ch = 4 * wid + sub;
            const int p  = saddr(ch, 2 * lane);     // even, 8B-aligned
            const float2 w2 = *(const float2*)&sw[p];
            const float2 k2 = *(const float2*)&sk[p];
            const float2 v2 = *(const float2*)&sv[p];
            const float2 r2 = *(const float2*)&sr[p];

            const float d0  = __expf(-__expf(w2.x));
            const float d1  = __expf(-__expf(w2.y));
            const float e0  = __expf(k2.x);
            const float e1  = __expf(k2.y);
            const float ev0 = e0 * v2.x;
            const float ev1 = e1 * v2.y;

            // lane-local composition of 2 steps (t0 then t1)
            float D = d0 * d1;
            float A = fmaf(ev0, d1, ev1);
            float Bv = fmaf(e0, d1, e1);

            // inclusive Kogge-Stone over lane aggregates
#pragma unroll
            for (int s = 1; s < 32; s <<= 1) {
                const float Dp = __shfl_up_sync(0xffffffffu, D, s);
                const float Ap = __shfl_up_sync(0xffffffffu, A, s);
                const float Bp = __shfl_up_sync(0xffffffffu, Bv, s);
                if (lane >= s) {
                    A  = fmaf(Ap, D, A);
                    Bv = fmaf(Bp, D, Bv);
                    D *= Dp;
                }
            }
            // exclusive prefix for this lane
            float Dx = __shfl_up_sync(0xffffffffu, D, 1);
            float Ax = __shfl_up_sync(0xffffffffu, A, 1);
            float Bx = __shfl_up_sync(0xffffffffu, Bv, 1);
            if (lane == 0) { Dx = 1.f; Ax = 0.f; Bx = 0.f; }
            const float Ain = fmaf(aC[sub], Dx, Ax);
            const float Bin = fmaf(bC[sub], Dx, Bx);

            // carry update from lane 31 inclusive aggregate
            const float D31 = __shfl_sync(0xffffffffu, D, 31);
            const float A31 = __shfl_sync(0xffffffffu, A, 31);
            const float B31 = __shfl_sync(0xffffffffu, Bv, 31);
            aC[sub] = fmaf(aC[sub], D31, A31);
            bC[sub] = fmaf(bC[sub], D31, B31);

            // replay the 2 local steps, emit
            const float a0 = fmaf(Ain, d0, ev0);
            const float b0 = fmaf(Bin, d0, e0);
            const float o0 = __fdividef(a0, (1.f + __expf(-r2.x)) * (b0 + WKV_EPS));
            const float a1 = fmaf(a0, d1, ev1);
            const float b1 = fmaf(b0, d1, e1);
            const float o1 = __fdividef(a1, (1.f + __expf(-r2.y)) * (b1 + WKV_EPS));
            *(float2*)&so[p] = make_float2(o0, o1);
        }
        __syncthreads();

        // ---- transposed read-back + coalesced float4 store ----
#pragma unroll
        for (int rr = 0; rr < 2; ++rr) {
            const int t = tl + rr * 32;
            float4 o;
#pragma unroll
            for (int j = 0; j < 4; ++j)
                ((float*)&o)[j] = so[saddr(4 * cl4 + j, t)];
            __stcs(&out[gco + (it * TTILE + t) * rowF4], o);
        }
        // so is re-written only after next iteration's first __syncthreads().
    }
}

extern "C" void kernel_launch(void* const* d_in, const int* in_sizes, int n_in,
                              void* d_out, int out_size) {
    const float4* r = (const float4*)d_in[0];
    const float4* w = (const float4*)d_in[1];
    const float4* k = (const float4*)d_in[2];
    const float4* v = (const float4*)d_in[3];
    float4* o = (float4*)d_out;

    cudaFuncSetAttribute(wkv_scan2,
                         cudaFuncAttributeMaxDynamicSharedMemorySize, SMEMB);
    const int grid = B_ * (C_ / CBLK);    // 256 CTAs
    wkv_scan2<<<grid, THREADS, SMEMB>>>(r, w, k, v, o);
}